// round 1
// baseline (speedup 1.0000x reference)
#include <cuda_runtime.h>

#define B_  32
#define NN  512
#define TT  24
#define FF  64
#define FA  74
#define TF  1536      // TT*FF
#define OUTROW 1776   // TT*FA

// small precomputed tensors
__device__ float g_RW[FA];
__device__ float g_W2[TT * TT];
__device__ float g_sigA[NN];

// ---------------------------------------------------------------------------
// Prep: RW[m] = sum_k w[m,k]*clip(d[k])*colsum_w[k]
//       W2eff[t][t'] = sum_k w2[t,k]*clip(d2[k])*w2[t',k]
//       sigA[n] = sigmoid(alpha[n])
// ---------------------------------------------------------------------------
__global__ void prep_kernel(const float* __restrict__ alpha,
                            const float* __restrict__ w,
                            const float* __restrict__ d,
                            const float* __restrict__ w2,
                            const float* __restrict__ d2) {
    __shared__ float colsum[FA];
    __shared__ float dc[FA];
    int tid = threadIdx.x;  // 256 threads

    for (int n = tid; n < NN; n += 256)
        g_sigA[n] = 1.0f / (1.0f + expf(-alpha[n]));

    if (tid < FA) {
        float s = 0.f;
        for (int n = 0; n < FA; n++) s += w[n * FA + tid];
        colsum[tid] = s;
        dc[tid] = fminf(fmaxf(d[tid], 0.f), 1.f);
    }
    __syncthreads();
    if (tid < FA) {
        float s = 0.f;
        for (int k = 0; k < FA; k++) s += w[tid * FA + k] * dc[k] * colsum[k];
        g_RW[tid] = s;
    }
    for (int idx = tid; idx < TT * TT; idx += 256) {
        int t = idx / TT, tp = idx % TT;
        float s = 0.f;
        for (int k = 0; k < TT; k++) {
            float dk = fminf(fmaxf(d2[k], 0.f), 1.f);
            s += w2[t * TT + k] * dk * w2[tp * TT + k];
        }
        g_W2[idx] = s;
    }
}

// ---------------------------------------------------------------------------
// Base: one block per (b,n) row.
//   base[t',f<64] = 0.5*x + 0.25*sum_t x[t,f]*W2[t,t'] + 0.25*S[t']*RW[f]
//   out[t',f>=64] = relu(0.25*S[t']*RW[f])   (final; GEMM kernel won't touch)
// base for f<64 is stored RAW into out; the GEMM kernel adds xa and relu's.
// ---------------------------------------------------------------------------
__global__ void base_kernel(const float* __restrict__ x, float* __restrict__ out) {
    int row = blockIdx.x;  // 0..B_*NN-1
    const float* xr = x + (size_t)row * TF;
    float* outr = out + (size_t)row * OUTROW;

    __shared__ float xs[TF];
    __shared__ float S[TT];
    __shared__ float W2s[TT * TT];
    __shared__ float RWs[FA];

    int tid = threadIdx.x;  // 256
    for (int idx = tid; idx < TF / 4; idx += 256)
        ((float4*)xs)[idx] = ((const float4*)xr)[idx];
    for (int idx = tid; idx < TT * TT; idx += 256) W2s[idx] = g_W2[idx];
    if (tid < FA) RWs[tid] = g_RW[tid];
    __syncthreads();

    if (tid < TT) {
        float s = 0.f;
        #pragma unroll
        for (int f = 0; f < FF; f++) s += xs[tid * FF + f];
        S[tid] = s;
    }
    __syncthreads();

    for (int idx = tid; idx < TF; idx += 256) {
        int tp = idx >> 6, f = idx & 63;
        float acc = 0.f;
        #pragma unroll
        for (int t = 0; t < TT; t++)
            acc = fmaf(xs[t * FF + f], W2s[t * TT + tp], acc);
        float base = 0.5f * xs[idx] + 0.25f * acc + 0.25f * S[tp] * RWs[f];
        outr[tp * FA + f] = base;
    }
    for (int idx = tid; idx < TT * (FA - FF); idx += 256) {
        int tp = idx / (FA - FF);
        int f  = FF + idx % (FA - FF);
        float v = 0.25f * S[tp] * RWs[f];
        outr[tp * FA + f] = fmaxf(v, 0.f);
    }
}

// ---------------------------------------------------------------------------
// GEMM: per batch b, C = adj(512x512) @ x[b](512x1536), tiled 128x128x16.
// Epilogue: out = relu(base + 0.125*sigA[i]*C[i,c]) for f<64 region.
// ---------------------------------------------------------------------------
__global__ __launch_bounds__(256, 2)
void gemm_kernel(const float* __restrict__ x, const float* __restrict__ adj,
                 float* __restrict__ out) {
    int b  = blockIdx.z;
    int i0 = blockIdx.y * 128;
    int c0 = blockIdx.x * 128;
    const float* Xb = x + (size_t)b * NN * TF;

    __shared__ float As[16][132];  // [k][i], padded
    __shared__ float Bs[16][128];  // [k][c]

    int tid = threadIdx.x;
    int tx = tid & 15, ty = tid >> 4;

    float acc[8][8];
    #pragma unroll
    for (int r = 0; r < 8; r++)
        #pragma unroll
        for (int c = 0; c < 8; c++) acc[r][c] = 0.f;

    for (int k0 = 0; k0 < NN; k0 += 16) {
        #pragma unroll
        for (int u = 0; u < 2; u++) {
            int idx = u * 256 + tid;
            int ar = idx >> 2, ac4 = idx & 3;
            float4 av = *(const float4*)&adj[(size_t)(i0 + ar) * NN + k0 + ac4 * 4];
            As[ac4 * 4 + 0][ar] = av.x;
            As[ac4 * 4 + 1][ar] = av.y;
            As[ac4 * 4 + 2][ar] = av.z;
            As[ac4 * 4 + 3][ar] = av.w;
            int br = idx >> 5, bc4 = idx & 31;
            float4 bv = *(const float4*)&Xb[(size_t)(k0 + br) * TF + c0 + bc4 * 4];
            *(float4*)&Bs[br][bc4 * 4] = bv;
        }
        __syncthreads();
        #pragma unroll
        for (int k = 0; k < 16; k++) {
            float a[8], bb[8];
            *(float4*)&a[0]  = *(float4*)&As[k][ty * 4];
            *(float4*)&a[4]  = *(float4*)&As[k][64 + ty * 4];
            *(float4*)&bb[0] = *(float4*)&Bs[k][tx * 4];
            *(float4*)&bb[4] = *(float4*)&Bs[k][64 + tx * 4];
            #pragma unroll
            for (int r = 0; r < 8; r++)
                #pragma unroll
                for (int c = 0; c < 8; c++)
                    acc[r][c] = fmaf(a[r], bb[c], acc[r][c]);
        }
        __syncthreads();
    }

    // epilogue: read base from out, add scaled xa, relu, write back
    #pragma unroll
    for (int r = 0; r < 8; r++) {
        int i = i0 + ((r < 4) ? (ty * 4 + r) : (64 + ty * 4 + r - 4));
        float coef = 0.125f * g_sigA[i];
        size_t rowbase = ((size_t)(b * NN + i)) * OUTROW;
        #pragma unroll
        for (int cq = 0; cq < 2; cq++) {
            int c = c0 + ((cq == 0) ? (tx * 4) : (64 + tx * 4));
            int t = c >> 6, f = c & 63;
            size_t o = rowbase + (size_t)t * FA + f;
            #pragma unroll
            for (int q = 0; q < 4; q += 2) {
                float2 basev = *(float2*)&out[o + q];
                float v0 = fmaxf(basev.x + coef * acc[r][cq * 4 + q],     0.f);
                float v1 = fmaxf(basev.y + coef * acc[r][cq * 4 + q + 1], 0.f);
                *(float2*)&out[o + q] = make_float2(v0, v1);
            }
        }
    }
}

extern "C" void kernel_launch(void* const* d_in, const int* in_sizes, int n_in,
                              void* d_out, int out_size) {
    const float* x     = (const float*)d_in[0];
    const float* adj   = (const float*)d_in[1];
    const float* alpha = (const float*)d_in[2];
    const float* w     = (const float*)d_in[3];
    const float* d     = (const float*)d_in[4];
    const float* w2    = (const float*)d_in[5];
    const float* d2    = (const float*)d_in[6];
    float* out = (float*)d_out;

    prep_kernel<<<1, 256>>>(alpha, w, d, w2, d2);
    base_kernel<<<B_ * NN, 256>>>(x, out);
    dim3 grid(TF / 128, NN / 128, B_);
    gemm_kernel<<<grid, 256>>>(x, adj, out);
}

// round 3
// speedup vs baseline: 2.1734x; 2.1734x over previous
#include <cuda_runtime.h>
#include <cuda_bf16.h>
#include <cstdint>

#define B_  32
#define NN  512
#define TT  24
#define FF  64
#define FA  74
#define TF  1536      // TT*FF
#define OUTROW 1776   // TT*FA

#define BM 128
#define BN 128
#define BK 32
#define NK (NN / BK)  // 16

#define AS_STRIDE 40   // halves per A row (32 data + 8 pad) = 80B
#define BS_STRIDE 136  // halves per B row (128 data + 8 pad) = 272B

__device__ float g_RW[FA];
__device__ float g_W2[TT * TT];
__device__ float g_sigA[NN];
__device__ __nv_bfloat16 g_y[(size_t)B_ * NN * TF];

// ---------------------------------------------------------------------------
__device__ __forceinline__ uint32_t smem_u32(const void* p) {
    uint32_t a;
    asm("{ .reg .u64 t; cvta.to.shared.u64 t, %1; cvt.u32.u64 %0, t; }" : "=r"(a) : "l"(p));
    return a;
}
__device__ __forceinline__ void ldsm4(uint32_t* r, uint32_t addr) {
    asm volatile("ldmatrix.sync.aligned.m8n8.x4.shared.b16 {%0,%1,%2,%3}, [%4];"
                 : "=r"(r[0]), "=r"(r[1]), "=r"(r[2]), "=r"(r[3]) : "r"(addr));
}
__device__ __forceinline__ void ldsm4t(uint32_t* r, uint32_t addr) {
    asm volatile("ldmatrix.sync.aligned.m8n8.x4.trans.shared.b16 {%0,%1,%2,%3}, [%4];"
                 : "=r"(r[0]), "=r"(r[1]), "=r"(r[2]), "=r"(r[3]) : "r"(addr));
}
__device__ __forceinline__ void mma16816(float* c, const uint32_t* a, const uint32_t* b) {
    asm volatile(
        "mma.sync.aligned.m16n8k16.row.col.f32.bf16.bf16.f32 "
        "{%0,%1,%2,%3}, {%4,%5,%6,%7}, {%8,%9}, {%0,%1,%2,%3};"
        : "+f"(c[0]), "+f"(c[1]), "+f"(c[2]), "+f"(c[3])
        : "r"(a[0]), "r"(a[1]), "r"(a[2]), "r"(a[3]), "r"(b[0]), "r"(b[1]));
}

// ---------------------------------------------------------------------------
// Prep
// ---------------------------------------------------------------------------
__global__ void prep_kernel(const float* __restrict__ alpha,
                            const float* __restrict__ w,
                            const float* __restrict__ d,
                            const float* __restrict__ w2,
                            const float* __restrict__ d2) {
    __shared__ float colsum[FA];
    __shared__ float dc[FA];
    int tid = threadIdx.x;  // 256

    for (int n = tid; n < NN; n += 256)
        g_sigA[n] = 1.0f / (1.0f + expf(-alpha[n]));

    if (tid < FA) {
        float s = 0.f;
        for (int n = 0; n < FA; n++) s += w[n * FA + tid];
        colsum[tid] = s;
        dc[tid] = fminf(fmaxf(d[tid], 0.f), 1.f);
    }
    __syncthreads();
    if (tid < FA) {
        float s = 0.f;
        for (int k = 0; k < FA; k++) s += w[tid * FA + k] * dc[k] * colsum[k];
        g_RW[tid] = s;
    }
    for (int idx = tid; idx < TT * TT; idx += 256) {
        int t = idx / TT, tp = idx % TT;
        float s = 0.f;
        for (int k = 0; k < TT; k++) {
            float dk = fminf(fmaxf(d2[k], 0.f), 1.f);
            s += w2[t * TT + k] * dk * w2[tp * TT + k];
        }
        g_W2[idx] = s;
    }
}

// ---------------------------------------------------------------------------
// mma.sync GEMM: y[b,i,c] = sum_k adj[i,k] * x[b,k,c]  (bf16 in, fp32 acc)
// CTA 128x128x(K=512, 32/stage), 8 warps in 2(m) x 4(n), warp tile 64x32.
// ---------------------------------------------------------------------------
__global__ __launch_bounds__(256)
void gemm_kernel(const float* __restrict__ x, const float* __restrict__ adj) {
    __shared__ __nv_bfloat16 As[2][BM * AS_STRIDE];
    __shared__ __nv_bfloat16 Bs[2][BK * BS_STRIDE];

    int tid = threadIdx.x, l = tid & 31, wid = tid >> 5;
    int wm = wid & 1, wn = wid >> 1;
    int b = blockIdx.z, i0 = blockIdx.y * BM, c0 = blockIdx.x * BN;
    const float* Xb = x + (size_t)b * NN * TF;

    uint32_t asb = smem_u32(As);
    uint32_t bsb = smem_u32(Bs);

    // LDG assignments
    int arow = tid >> 1, acol = (tid & 1) * 16;          // A: 128 rows x 32
    int brow = tid >> 3, bcol = (tid & 7) * 16;          // B: 32 rows x 128
    const float* aptr = adj + (size_t)(i0 + arow) * NN + acol;
    const float* bptr = Xb + (size_t)brow * TF + c0 + bcol;

    uint32_t gA[8], gB[8];

#define LDG_STAGE(s)                                                          \
    {                                                                         \
        const float4* pa = (const float4*)(aptr + (s) * BK);                  \
        const float4* pb = (const float4*)(bptr + (size_t)(s) * BK * TF);     \
        _Pragma("unroll")                                                     \
        for (int j = 0; j < 4; j++) {                                         \
            float4 v = pa[j];                                                 \
            __nv_bfloat162 h0 = __float22bfloat162_rn(make_float2(v.x, v.y)); \
            __nv_bfloat162 h1 = __float22bfloat162_rn(make_float2(v.z, v.w)); \
            gA[2 * j] = *(uint32_t*)&h0; gA[2 * j + 1] = *(uint32_t*)&h1;     \
            float4 u = pb[j];                                                 \
            __nv_bfloat162 q0 = __float22bfloat162_rn(make_float2(u.x, u.y)); \
            __nv_bfloat162 q1 = __float22bfloat162_rn(make_float2(u.z, u.w)); \
            gB[2 * j] = *(uint32_t*)&q0; gB[2 * j + 1] = *(uint32_t*)&q1;     \
        }                                                                     \
    }

#define STS_STAGE(buf)                                                        \
    {                                                                         \
        uint32_t a0 = asb + (uint32_t)(buf) * (BM * AS_STRIDE * 2)            \
                      + arow * (AS_STRIDE * 2) + acol * 2;                    \
        asm volatile("st.shared.v4.b32 [%0],{%1,%2,%3,%4};" ::"r"(a0),        \
                     "r"(gA[0]), "r"(gA[1]), "r"(gA[2]), "r"(gA[3]) : "memory"); \
        asm volatile("st.shared.v4.b32 [%0],{%1,%2,%3,%4};" ::"r"(a0 + 16),   \
                     "r"(gA[4]), "r"(gA[5]), "r"(gA[6]), "r"(gA[7]) : "memory"); \
        uint32_t b0 = bsb + (uint32_t)(buf) * (BK * BS_STRIDE * 2)            \
                      + brow * (BS_STRIDE * 2) + bcol * 2;                    \
        asm volatile("st.shared.v4.b32 [%0],{%1,%2,%3,%4};" ::"r"(b0),        \
                     "r"(gB[0]), "r"(gB[1]), "r"(gB[2]), "r"(gB[3]) : "memory"); \
        asm volatile("st.shared.v4.b32 [%0],{%1,%2,%3,%4};" ::"r"(b0 + 16),   \
                     "r"(gB[4]), "r"(gB[5]), "r"(gB[6]), "r"(gB[7]) : "memory"); \
    }

    float acc[4][4][4];
    #pragma unroll
    for (int mt = 0; mt < 4; mt++)
        #pragma unroll
        for (int nt = 0; nt < 4; nt++)
            #pragma unroll
            for (int q = 0; q < 4; q++) acc[mt][nt][q] = 0.f;

    // ldmatrix address bases (within a stage)
    uint32_t a_off = (uint32_t)(wm * 64 + (l & 15)) * (AS_STRIDE * 2) + ((l >> 4) * 8) * 2;
    uint32_t b_off = (uint32_t)(l & 15) * (BS_STRIDE * 2) + (wn * 32 + ((l >> 4) << 3)) * 2;

    LDG_STAGE(0);
    STS_STAGE(0);
    LDG_STAGE(1);
    __syncthreads();

    for (int s = 0; s < NK; s++) {
        int buf = s & 1;
        if (s + 1 < NK) STS_STAGE(buf ^ 1);
        if (s + 2 < NK) LDG_STAGE(s + 2);

        uint32_t ab = asb + buf * (BM * AS_STRIDE * 2) + a_off;
        uint32_t bb = bsb + buf * (BK * BS_STRIDE * 2) + b_off;
        #pragma unroll
        for (int ks = 0; ks < 2; ks++) {
            uint32_t af[4][4], bf[2][4];
            #pragma unroll
            for (int mt = 0; mt < 4; mt++)
                ldsm4(af[mt], ab + mt * 16 * (AS_STRIDE * 2) + ks * 32);
            #pragma unroll
            for (int n2 = 0; n2 < 2; n2++)
                ldsm4t(bf[n2], bb + ks * 16 * (BS_STRIDE * 2) + n2 * 32);
            #pragma unroll
            for (int mt = 0; mt < 4; mt++)
                #pragma unroll
                for (int nt = 0; nt < 4; nt++)
                    mma16816(acc[mt][nt], af[mt], &bf[nt >> 1][(nt & 1) * 2]);
        }
        __syncthreads();
    }

    // epilogue: fragments -> bf16 y
    int rbase = i0 + wm * 64 + (l >> 2);
    int cbase = c0 + wn * 32 + (l & 3) * 2;
    #pragma unroll
    for (int mt = 0; mt < 4; mt++) {
        #pragma unroll
        for (int nt = 0; nt < 4; nt++) {
            int i = rbase + mt * 16;
            int c = cbase + nt * 8;
            __nv_bfloat162 h0 = __float22bfloat162_rn(make_float2(acc[mt][nt][0], acc[mt][nt][1]));
            __nv_bfloat162 h1 = __float22bfloat162_rn(make_float2(acc[mt][nt][2], acc[mt][nt][3]));
            *(__nv_bfloat162*)&g_y[((size_t)b * NN + i) * TF + c] = h0;
            *(__nv_bfloat162*)&g_y[((size_t)b * NN + i + 8) * TF + c] = h1;
        }
    }
}

// ---------------------------------------------------------------------------
// Combine: out = relu(0.5*x + 0.25*xw2 + 0.25*S*RW + 0.125*sigA*y), plus f>=64.
// ---------------------------------------------------------------------------
__global__ __launch_bounds__(128)
void combine_kernel(const float* __restrict__ x, float* __restrict__ out) {
    int row = blockIdx.x;                // b*NN + node
    int node = row & (NN - 1);
    const float* xr = x + (size_t)row * TF;
    const __nv_bfloat16* yr = g_y + (size_t)row * TF;
    float* outr = out + (size_t)row * OUTROW;

    __shared__ float xs[TF];
    __shared__ __nv_bfloat16 ys[TF];
    __shared__ float W2s[TT * TT];
    __shared__ float S[TT];
    __shared__ float RWs[FA];

    int tid = threadIdx.x;  // 128
    #pragma unroll
    for (int j = 0; j < 3; j++)
        ((float4*)xs)[j * 128 + tid] = ((const float4*)xr)[j * 128 + tid];
    {
        int j = tid;
        if (j < 192) ((uint4*)ys)[j] = ((const uint4*)yr)[j];
        j = tid + 128;
        if (j < 192) ((uint4*)ys)[j] = ((const uint4*)yr)[j];
    }
    for (int j = tid; j < TT * TT; j += 128) W2s[j] = g_W2[j];
    if (tid < FA) RWs[tid] = g_RW[tid];
    __syncthreads();

    if (tid < TT) {
        float s = 0.f;
        #pragma unroll
        for (int f = 0; f < FF; f++) s += xs[tid * FF + f];
        S[tid] = s;
    }
    __syncthreads();

    float coef = 0.125f * g_sigA[node];
    #pragma unroll
    for (int j = 0; j < 12; j++) {
        int idx = j * 128 + tid;
        int tp = idx >> 6, f = idx & 63;
        float acc = 0.f;
        #pragma unroll
        for (int t = 0; t < TT; t++)
            acc = fmaf(xs[t * FF + f], W2s[t * TT + tp], acc);
        float v = 0.5f * xs[idx] + 0.25f * acc + 0.25f * S[tp] * RWs[f]
                + coef * __bfloat162float(ys[idx]);
        outr[tp * FA + f] = fmaxf(v, 0.f);
    }
    for (int idx = tid; idx < TT * (FA - FF); idx += 128) {
        int tp = idx / (FA - FF);
        int f  = FF + idx % (FA - FF);
        outr[tp * FA + f] = fmaxf(0.25f * S[tp] * RWs[f], 0.f);
    }
}

extern "C" void kernel_launch(void* const* d_in, const int* in_sizes, int n_in,
                              void* d_out, int out_size) {
    const float* x     = (const float*)d_in[0];
    const float* adj   = (const float*)d_in[1];
    const float* alpha = (const float*)d_in[2];
    const float* w     = (const float*)d_in[3];
    const float* d     = (const float*)d_in[4];
    const float* w2    = (const float*)d_in[5];
    const float* d2    = (const float*)d_in[6];
    float* out = (float*)d_out;

    prep_kernel<<<1, 256>>>(alpha, w, d, w2, d2);
    dim3 grid(TF / BN, NN / BM, B_);
    gemm_kernel<<<grid, 256>>>(x, adj);
    combine_kernel<<<B_ * NN, 128>>>(x, out);
}

// round 4
// speedup vs baseline: 2.6901x; 1.2377x over previous
#include <cuda_runtime.h>
#include <cuda_bf16.h>
#include <cstdint>

#define B_  32
#define NN  512
#define TT  24
#define FF  64
#define FA  74
#define TF  1536      // TT*FF
#define OUTROW 1776   // TT*FA

#define BM 128
#define BN 128
#define BK 32
#define NK (NN / BK)  // 16
#define STAGES 4

#define AS_STRIDE 40   // halves per A row (32 data + 8 pad) = 80B
#define BS_STRIDE 136  // halves per B row (128 data + 8 pad) = 272B
#define ASTG (BM * AS_STRIDE)   // bf16 elems per A stage (5120 -> 10240B)
#define BSTG (BK * BS_STRIDE)   // bf16 elems per B stage (4352 -> 8704B)
#define GEMM_SMEM (STAGES * (ASTG + BSTG) * 2)  // 75776 B

__device__ float g_RW[FA];
__device__ float g_W2[TT * TT];
__device__ float g_sigA[NN];
__device__ __nv_bfloat16 g_y[(size_t)B_ * NN * TF];
__device__ __nv_bfloat16 g_xb[(size_t)B_ * NN * TF];
__device__ __nv_bfloat16 g_adjb[(size_t)NN * NN];

// ---------------------------------------------------------------------------
__device__ __forceinline__ uint32_t smem_u32(const void* p) {
    uint32_t a;
    asm("{ .reg .u64 t; cvta.to.shared.u64 t, %1; cvt.u32.u64 %0, t; }" : "=r"(a) : "l"(p));
    return a;
}
__device__ __forceinline__ void ldsm4(uint32_t* r, uint32_t addr) {
    asm volatile("ldmatrix.sync.aligned.m8n8.x4.shared.b16 {%0,%1,%2,%3}, [%4];"
                 : "=r"(r[0]), "=r"(r[1]), "=r"(r[2]), "=r"(r[3]) : "r"(addr));
}
__device__ __forceinline__ void ldsm4t(uint32_t* r, uint32_t addr) {
    asm volatile("ldmatrix.sync.aligned.m8n8.x4.trans.shared.b16 {%0,%1,%2,%3}, [%4];"
                 : "=r"(r[0]), "=r"(r[1]), "=r"(r[2]), "=r"(r[3]) : "r"(addr));
}
__device__ __forceinline__ void mma16816(float* c, const uint32_t* a, const uint32_t* b) {
    asm volatile(
        "mma.sync.aligned.m16n8k16.row.col.f32.bf16.bf16.f32 "
        "{%0,%1,%2,%3}, {%4,%5,%6,%7}, {%8,%9}, {%0,%1,%2,%3};"
        : "+f"(c[0]), "+f"(c[1]), "+f"(c[2]), "+f"(c[3])
        : "r"(a[0]), "r"(a[1]), "r"(a[2]), "r"(a[3]), "r"(b[0]), "r"(b[1]));
}
#define CP16(dst, src) \
    asm volatile("cp.async.cg.shared.global [%0], [%1], 16;" :: "r"(dst), "l"(src) : "memory")
#define CP_COMMIT() asm volatile("cp.async.commit_group;" ::: "memory")
#define CP_WAIT2()  asm volatile("cp.async.wait_group 2;" ::: "memory")

// ---------------------------------------------------------------------------
// Converts
// ---------------------------------------------------------------------------
__global__ void convert_x_kernel(const float* __restrict__ x) {
    size_t i = (size_t)blockIdx.x * 256 + threadIdx.x;   // one per 8 floats
    const float4* src = (const float4*)x + i * 2;
    float4 a = src[0], b = src[1];
    __nv_bfloat162 h0 = __float22bfloat162_rn(make_float2(a.x, a.y));
    __nv_bfloat162 h1 = __float22bfloat162_rn(make_float2(a.z, a.w));
    __nv_bfloat162 h2 = __float22bfloat162_rn(make_float2(b.x, b.y));
    __nv_bfloat162 h3 = __float22bfloat162_rn(make_float2(b.z, b.w));
    ((uint4*)g_xb)[i] = make_uint4(*(uint32_t*)&h0, *(uint32_t*)&h1,
                                   *(uint32_t*)&h2, *(uint32_t*)&h3);
}
__global__ void convert_adj_kernel(const float* __restrict__ adj) {
    size_t i = (size_t)blockIdx.x * 256 + threadIdx.x;
    const float4* src = (const float4*)adj + i * 2;
    float4 a = src[0], b = src[1];
    __nv_bfloat162 h0 = __float22bfloat162_rn(make_float2(a.x, a.y));
    __nv_bfloat162 h1 = __float22bfloat162_rn(make_float2(a.z, a.w));
    __nv_bfloat162 h2 = __float22bfloat162_rn(make_float2(b.x, b.y));
    __nv_bfloat162 h3 = __float22bfloat162_rn(make_float2(b.z, b.w));
    ((uint4*)g_adjb)[i] = make_uint4(*(uint32_t*)&h0, *(uint32_t*)&h1,
                                     *(uint32_t*)&h2, *(uint32_t*)&h3);
}

// ---------------------------------------------------------------------------
// Prep
// ---------------------------------------------------------------------------
__global__ void prep_kernel(const float* __restrict__ alpha,
                            const float* __restrict__ w,
                            const float* __restrict__ d,
                            const float* __restrict__ w2,
                            const float* __restrict__ d2) {
    __shared__ float colsum[FA];
    __shared__ float dc[FA];
    int tid = threadIdx.x;  // 256

    for (int n = tid; n < NN; n += 256)
        g_sigA[n] = 1.0f / (1.0f + expf(-alpha[n]));

    if (tid < FA) {
        float s = 0.f;
        for (int n = 0; n < FA; n++) s += w[n * FA + tid];
        colsum[tid] = s;
        dc[tid] = fminf(fmaxf(d[tid], 0.f), 1.f);
    }
    __syncthreads();
    if (tid < FA) {
        float s = 0.f;
        for (int k = 0; k < FA; k++) s += w[tid * FA + k] * dc[k] * colsum[k];
        g_RW[tid] = s;
    }
    for (int idx = tid; idx < TT * TT; idx += 256) {
        int t = idx / TT, tp = idx % TT;
        float s = 0.f;
        for (int k = 0; k < TT; k++) {
            float dk = fminf(fmaxf(d2[k], 0.f), 1.f);
            s += w2[t * TT + k] * dk * w2[tp * TT + k];
        }
        g_W2[idx] = s;
    }
}

// ---------------------------------------------------------------------------
// cp.async mma.sync GEMM: y[b,i,c] = sum_k adj[i,k]*x[b,k,c]  (bf16, fp32 acc)
// 4-stage cp.async pipeline, CTA 128x128, 8 warps 2(m)x4(n), warp tile 64x32.
// ---------------------------------------------------------------------------
__global__ __launch_bounds__(256)
void gemm_kernel() {
    extern __shared__ __nv_bfloat16 smem[];
    __nv_bfloat16* As = smem;
    __nv_bfloat16* Bs = smem + STAGES * ASTG;

    int tid = threadIdx.x, l = tid & 31, wid = tid >> 5;
    int wm = wid & 1, wn = wid >> 1;
    int b = blockIdx.z, i0 = blockIdx.y * BM, c0 = blockIdx.x * BN;
    const __nv_bfloat16* Xb = g_xb + (size_t)b * NN * TF;

    uint32_t asb = smem_u32(As);
    uint32_t bsb = smem_u32(Bs);

#define ISSUE_STAGE(s)                                                         \
    {                                                                          \
        int buf_ = (s) & (STAGES - 1);                                         \
        int k0_ = (s) * BK;                                                    \
        uint32_t ab_ = asb + buf_ * (ASTG * 2);                                \
        uint32_t bb_ = bsb + buf_ * (BSTG * 2);                                \
        _Pragma("unroll")                                                      \
        for (int u = 0; u < 2; u++) {                                          \
            int id = u * 256 + tid;                                            \
            int ar = id >> 2, ac = id & 3;                                     \
            CP16(ab_ + ar * 80 + ac * 16,                                      \
                 (const char*)(g_adjb + (size_t)(i0 + ar) * NN + k0_) + ac * 16); \
            int br = id >> 4, bc = id & 15;                                    \
            CP16(bb_ + br * 272 + bc * 16,                                     \
                 (const char*)(Xb + (size_t)(k0_ + br) * TF + c0) + bc * 16);  \
        }                                                                      \
    }

    float acc[4][4][4];
    #pragma unroll
    for (int mt = 0; mt < 4; mt++)
        #pragma unroll
        for (int nt = 0; nt < 4; nt++)
            #pragma unroll
            for (int q = 0; q < 4; q++) acc[mt][nt][q] = 0.f;

    uint32_t a_off = (uint32_t)(wm * 64 + (l & 15)) * 80 + ((l >> 4) * 8) * 2;
    uint32_t b_off = (uint32_t)(l & 15) * 272 + (wn * 32 + ((l >> 4) << 3)) * 2;

    ISSUE_STAGE(0); CP_COMMIT();
    ISSUE_STAGE(1); CP_COMMIT();
    ISSUE_STAGE(2); CP_COMMIT();

    for (int s = 0; s < NK; s++) {
        int buf = s & (STAGES - 1);
        CP_WAIT2();
        __syncthreads();

        if (s + 3 < NK) ISSUE_STAGE(s + 3);
        CP_COMMIT();   // always commit so wait_group 2 tracks stage s exactly

        uint32_t ab = asb + buf * (ASTG * 2) + a_off;
        uint32_t bb = bsb + buf * (BSTG * 2) + b_off;
        #pragma unroll
        for (int ks = 0; ks < 2; ks++) {
            uint32_t af[4][4], bf[2][4];
            #pragma unroll
            for (int mt = 0; mt < 4; mt++)
                ldsm4(af[mt], ab + mt * 16 * 80 + ks * 32);
            #pragma unroll
            for (int n2 = 0; n2 < 2; n2++)
                ldsm4t(bf[n2], bb + ks * 16 * 272 + n2 * 32);
            #pragma unroll
            for (int mt = 0; mt < 4; mt++)
                #pragma unroll
                for (int nt = 0; nt < 4; nt++)
                    mma16816(acc[mt][nt], af[mt], &bf[nt >> 1][(nt & 1) * 2]);
        }
        __syncthreads();
    }

    // epilogue: fragments -> bf16 y
    int rbase = i0 + wm * 64 + (l >> 2);
    int cbase = c0 + wn * 32 + (l & 3) * 2;
    #pragma unroll
    for (int mt = 0; mt < 4; mt++) {
        #pragma unroll
        for (int nt = 0; nt < 4; nt++) {
            int i = rbase + mt * 16;
            int c = cbase + nt * 8;
            __nv_bfloat162 h0 = __float22bfloat162_rn(make_float2(acc[mt][nt][0], acc[mt][nt][1]));
            __nv_bfloat162 h1 = __float22bfloat162_rn(make_float2(acc[mt][nt][2], acc[mt][nt][3]));
            *(__nv_bfloat162*)&g_y[((size_t)b * NN + i) * TF + c] = h0;
            *(__nv_bfloat162*)&g_y[((size_t)b * NN + i + 8) * TF + c] = h1;
        }
    }
}

// ---------------------------------------------------------------------------
// Combine: out = relu(0.5*x + 0.25*xw2 + 0.25*S*RW + 0.125*sigA*y), plus f>=64.
// ---------------------------------------------------------------------------
__global__ __launch_bounds__(128)
void combine_kernel(const float* __restrict__ x, float* __restrict__ out) {
    int row = blockIdx.x;                // b*NN + node
    int node = row & (NN - 1);
    const float* xr = x + (size_t)row * TF;
    const __nv_bfloat16* yr = g_y + (size_t)row * TF;
    float* outr = out + (size_t)row * OUTROW;

    __shared__ float xs[TF];
    __shared__ __nv_bfloat16 ys[TF];
    __shared__ float W2s[TT * TT];
    __shared__ float S[TT];
    __shared__ float RWs[FA];

    int tid = threadIdx.x;  // 128
    #pragma unroll
    for (int j = 0; j < 3; j++)
        ((float4*)xs)[j * 128 + tid] = ((const float4*)xr)[j * 128 + tid];
    {
        int j = tid;
        if (j < 192) ((uint4*)ys)[j] = ((const uint4*)yr)[j];
        j = tid + 128;
        if (j < 192) ((uint4*)ys)[j] = ((const uint4*)yr)[j];
    }
    for (int j = tid; j < TT * TT; j += 128) W2s[j] = g_W2[j];
    if (tid < FA) RWs[tid] = g_RW[tid];
    __syncthreads();

    if (tid < TT) {
        float s = 0.f;
        #pragma unroll
        for (int f = 0; f < FF; f++) s += xs[tid * FF + f];
        S[tid] = s;
    }
    __syncthreads();

    float coef = 0.125f * g_sigA[node];
    #pragma unroll
    for (int j = 0; j < 12; j++) {
        int idx = j * 128 + tid;
        int tp = idx >> 6, f = idx & 63;
        float acc = 0.f;
        #pragma unroll
        for (int t = 0; t < TT; t++)
            acc = fmaf(xs[t * FF + f], W2s[t * TT + tp], acc);
        float v = 0.5f * xs[idx] + 0.25f * acc + 0.25f * S[tp] * RWs[f]
                + coef * __bfloat162float(ys[idx]);
        outr[tp * FA + f] = fmaxf(v, 0.f);
    }
    for (int idx = tid; idx < TT * (FA - FF); idx += 128) {
        int tp = idx / (FA - FF);
        int f  = FF + idx % (FA - FF);
        outr[tp * FA + f] = fmaxf(0.25f * S[tp] * RWs[f], 0.f);
    }
}

extern "C" void kernel_launch(void* const* d_in, const int* in_sizes, int n_in,
                              void* d_out, int out_size) {
    const float* x     = (const float*)d_in[0];
    const float* adj   = (const float*)d_in[1];
    const float* alpha = (const float*)d_in[2];
    const float* w     = (const float*)d_in[3];
    const float* d     = (const float*)d_in[4];
    const float* w2    = (const float*)d_in[5];
    const float* d2    = (const float*)d_in[6];
    float* out = (float*)d_out;

    cudaFuncSetAttribute(gemm_kernel, cudaFuncAttributeMaxDynamicSharedMemorySize, GEMM_SMEM);

    prep_kernel<<<1, 256>>>(alpha, w, d, w2, d2);
    convert_adj_kernel<<<(NN * NN / 8) / 256, 256>>>(adj);
    convert_x_kernel<<<((size_t)B_ * NN * TF / 8) / 256, 256>>>(x);
    dim3 grid(TF / BN, NN / BM, B_);
    gemm_kernel<<<grid, 256, GEMM_SMEM>>>();
    combine_kernel<<<B_ * NN, 128>>>(x, out);
}